// round 3
// baseline (speedup 1.0000x reference)
#include <cuda_runtime.h>
#include <mma.h>
#include <math.h>
#include <stdint.h>

using namespace nvcuda;

// Problem constants
#define C_     192
#define LDA    196          // padded row stride (floats), %4==0 for wmma, float4 rows bank-clean
#define HIDDEN 768
#define NPIX   (32*64*64)   // 131072 tokens

// scratch for first residual output y = x + attn_out
__device__ float g_y[(size_t)NPIX * C_];

// ---------------------------------------------------------------------------
// Kernel A: per-window  LN1 -> qkv GEMM -> global-query attention -> proj -> +x
// grid = 2048 windows, 512 threads, dynamic smem = 204800 B
// smem: sh_h[64][196] | sh_k[64][196] | sh_v[64][196] | sh_w[12544] | p_buf[16][64]
// ---------------------------------------------------------------------------
__global__ __launch_bounds__(512) void k_attn(
    const float* __restrict__ x,     const float* __restrict__ qg,
    const float* __restrict__ n1g,   const float* __restrict__ n1b,
    const float* __restrict__ qkvw,  const float* __restrict__ qkvb,
    const float* __restrict__ rpb,
    const float* __restrict__ projw, const float* __restrict__ projb)
{
    extern __shared__ __align__(128) float smem[];
    float* sh_h  = smem;            // 12544
    float* sh_k  = smem + 12544;
    float* sh_v  = smem + 25088;
    float* sh_w  = smem + 37632;    // staging: weights / q
    float* p_buf = smem + 50176;    // 16*64

    const int w  = blockIdx.x;
    const int b  = w >> 6, wy = (w >> 3) & 7, wx = w & 7;
    const int tid = threadIdx.x, lane = tid & 31, wp = tid >> 5;
    const int row0 = wy * 8, col0 = wx * 8;

    // ---------------- LN1 (warp per token, 4 tokens/warp) ----------------
    #pragma unroll
    for (int ni = 0; ni < 4; ni++) {
        const int n = wp * 4 + ni;
        const float* xp = x + ((size_t)((b * 64 + row0 + (n >> 3)) * 64 + col0 + (n & 7))) * C_;
        float v[6]; float s = 0.f, s2 = 0.f;
        #pragma unroll
        for (int j = 0; j < 6; j++) { v[j] = xp[lane + 32 * j]; s += v[j]; s2 += v[j] * v[j]; }
        #pragma unroll
        for (int o = 16; o > 0; o >>= 1) {
            s  += __shfl_xor_sync(0xffffffffu, s,  o);
            s2 += __shfl_xor_sync(0xffffffffu, s2, o);
        }
        const float mean = s * (1.f / 192.f);
        const float rstd = rsqrtf(fmaxf(s2 * (1.f / 192.f) - mean * mean, 0.f) + 1e-5f);
        #pragma unroll
        for (int j = 0; j < 6; j++) {
            const int c = lane + 32 * j;
            sh_h[n * LDA + c] = (v[j] - mean) * rstd * n1g[c] + n1b[c];
        }
    }
    __syncthreads();

    // ---------------- QKV GEMM: [64x192] @ [192x384] (tf32 wmma) ----------------
    // Weight tiles register-prefetched (double-buffered in RF) to overlap L2 fetch with MMA.
    {
        const int ctBase = (wp >> 1) * 3;   // 24 col tiles -> 3 per warp-pair
        const int mt0    = (wp & 1) * 2;    // 4 row tiles -> 2 per warp
        wmma::fragment<wmma::accumulator, 16, 16, 8, float> acc[6];
        #pragma unroll
        for (int i = 0; i < 6; i++) wmma::fill_fragment(acc[i], 0.f);

        // prologue: load kc=0 tile into registers (6 float4 per thread)
        float4 pre[6];
        #pragma unroll
        for (int i = 0; i < 6; i++) {
            const int idx = tid + 512 * i;
            const int r = idx / 96, c4 = (idx - r * 96) * 4;
            pre[i] = *(const float4*)(qkvw + r * 384 + c4);
        }

        for (int kc = 0; kc < 6; kc++) {
            const int k0 = kc * 32;
            // commit prefetched tile -> sh_w, row stride 392
            #pragma unroll
            for (int i = 0; i < 6; i++) {
                const int idx = tid + 512 * i;
                const int r = idx / 96, c4 = (idx - r * 96) * 4;
                *(float4*)(sh_w + r * 392 + c4) = pre[i];
            }
            __syncthreads();
            // prefetch next tile (overlaps with MMAs below)
            if (kc < 5) {
                #pragma unroll
                for (int i = 0; i < 6; i++) {
                    const int idx = tid + 512 * i;
                    const int r = idx / 96, c4 = (idx - r * 96) * 4;
                    pre[i] = *(const float4*)(qkvw + (k0 + 32 + r) * 384 + c4);
                }
            }
            #pragma unroll
            for (int kk = 0; kk < 4; kk++) {
                wmma::fragment<wmma::matrix_a, 16, 16, 8, wmma::precision::tf32, wmma::row_major> af[2];
                #pragma unroll
                for (int i = 0; i < 2; i++) {
                    wmma::load_matrix_sync(af[i], sh_h + (mt0 + i) * 16 * LDA + k0 + kk * 8, LDA);
                    #pragma unroll
                    for (int e = 0; e < af[i].num_elements; e++) af[i].x[e] = wmma::__float_to_tf32(af[i].x[e]);
                }
                #pragma unroll
                for (int j = 0; j < 3; j++) {
                    wmma::fragment<wmma::matrix_b, 16, 16, 8, wmma::precision::tf32, wmma::row_major> bf;
                    wmma::load_matrix_sync(bf, sh_w + kk * 8 * 392 + (ctBase + j) * 16, 392);
                    #pragma unroll
                    for (int e = 0; e < bf.num_elements; e++) bf.x[e] = wmma::__float_to_tf32(bf.x[e]);
                    #pragma unroll
                    for (int i = 0; i < 2; i++) wmma::mma_sync(acc[i * 3 + j], af[i], bf, acc[i * 3 + j]);
                }
            }
            __syncthreads();
        }
        #pragma unroll
        for (int i = 0; i < 2; i++)
            #pragma unroll
            for (int j = 0; j < 3; j++) {
                const int cg = (ctBase + j) * 16;
                float* dst = (cg < 192) ? (sh_k + (mt0 + i) * 16 * LDA + cg)
                                        : (sh_v + (mt0 + i) * 16 * LDA + (cg - 192));
                wmma::store_matrix_sync(dst, acc[i * 3 + j], LDA, wmma::mem_row_major);
            }
    }
    __syncthreads();

    // qkv bias + stage q*scale into sh_w ([head][n][d], compact)
    for (int idx = tid; idx < 3072; idx += 512) {
        const int n = idx / 48, c4 = (idx - n * 48) * 4;
        const float4 bk = *(const float4*)(qkvb + c4);
        const float4 bv = *(const float4*)(qkvb + 192 + c4);
        float* pk = sh_k + n * LDA + c4;
        float* pv = sh_v + n * LDA + c4;
        pk[0] += bk.x; pk[1] += bk.y; pk[2] += bk.z; pk[3] += bk.w;
        pv[0] += bv.x; pv[1] += bv.y; pv[2] += bv.z; pv[3] += bv.w;
    }
    for (int idx = tid; idx < 12288; idx += 512) {
        const int d = idx & 31, n = (idx >> 5) & 63, head = idx >> 11;
        sh_w[idx] = qg[(((size_t)b * 64 + n) * 6 + head) * 32 + d] * 0.17677669529663688f; // 1/sqrt(32)
    }
    __syncthreads();

    // ---------------- attention: 384 (head,row) tasks over 16 warps ----------------
    for (int it = 0; it < 24; it++) {
        const int t = wp + (it << 4);
        const int head = t >> 6, n = t & 63;
        const int hb = head << 5;
        const float4* q4 = (const float4*)(sh_w + (head << 11) + (n << 5));
        const int iy = n >> 3, ix = n & 7;
        float s01[2];
        #pragma unroll
        for (int half = 0; half < 2; half++) {
            const int m = lane + half * 32;
            const float4* kr = (const float4*)(sh_k + m * LDA + hb);
            float a0 = 0.f;
            #pragma unroll
            for (int d4 = 0; d4 < 8; d4++) {
                const float4 kk4 = kr[d4]; const float4 qq4 = q4[d4];
                a0 += kk4.x * qq4.x + kk4.y * qq4.y + kk4.z * qq4.z + kk4.w * qq4.w;
            }
            const int jy = m >> 3, jx = m & 7;
            s01[half] = a0 + rpb[((iy - jy + 7) * 15 + (ix - jx + 7)) * 6 + head];
        }
        float mx = fmaxf(s01[0], s01[1]);
        #pragma unroll
        for (int o = 16; o > 0; o >>= 1) mx = fmaxf(mx, __shfl_xor_sync(0xffffffffu, mx, o));
        const float e0 = __expf(s01[0] - mx), e1 = __expf(s01[1] - mx);
        float sm = e0 + e1;
        #pragma unroll
        for (int o = 16; o > 0; o >>= 1) sm += __shfl_xor_sync(0xffffffffu, sm, o);
        const float inv = 1.f / sm;
        p_buf[(wp << 6) + lane]      = e0 * inv;
        p_buf[(wp << 6) + lane + 32] = e1 * inv;
        __syncwarp();
        float oacc = 0.f;
        #pragma unroll 8
        for (int m = 0; m < 64; m++) oacc += p_buf[(wp << 6) + m] * sh_v[m * LDA + hb + lane];
        sh_h[n * LDA + hb + lane] = oacc;   // o overwrites h (free after qkv)
        __syncwarp();
    }
    __syncthreads();

    // ---------------- proj: o[64x192] @ proj_w[192x192] ----------------
    {
        const int mt  = wp >> 2;          // 4 row tiles
        const int ctB = (wp & 3) * 3;     // 12 col tiles -> 3/warp
        wmma::fragment<wmma::accumulator, 16, 16, 8, float> acc[3];
        #pragma unroll
        for (int j = 0; j < 3; j++) wmma::fill_fragment(acc[j], 0.f);

        float4 pre[6];
        #pragma unroll
        for (int i = 0; i < 6; i++) {
            const int idx = tid + 512 * i;
            const int r = idx / 48, c4 = (idx - r * 48) * 4;
            pre[i] = *(const float4*)(projw + r * 192 + c4);
        }

        for (int kc = 0; kc < 3; kc++) {
            const int k0 = kc * 64;
            #pragma unroll
            for (int i = 0; i < 6; i++) {
                const int idx = tid + 512 * i;
                const int r = idx / 48, c4 = (idx - r * 48) * 4;
                *(float4*)(sh_w + r * LDA + c4) = pre[i];
            }
            __syncthreads();
            if (kc < 2) {
                #pragma unroll
                for (int i = 0; i < 6; i++) {
                    const int idx = tid + 512 * i;
                    const int r = idx / 48, c4 = (idx - r * 48) * 4;
                    pre[i] = *(const float4*)(projw + (k0 + 64 + r) * 192 + c4);
                }
            }
            #pragma unroll
            for (int kk = 0; kk < 8; kk++) {
                wmma::fragment<wmma::matrix_a, 16, 16, 8, wmma::precision::tf32, wmma::row_major> af;
                wmma::load_matrix_sync(af, sh_h + mt * 16 * LDA + k0 + kk * 8, LDA);
                #pragma unroll
                for (int e = 0; e < af.num_elements; e++) af.x[e] = wmma::__float_to_tf32(af.x[e]);
                #pragma unroll
                for (int j = 0; j < 3; j++) {
                    wmma::fragment<wmma::matrix_b, 16, 16, 8, wmma::precision::tf32, wmma::row_major> bf;
                    wmma::load_matrix_sync(bf, sh_w + kk * 8 * LDA + (ctB + j) * 16, LDA);
                    #pragma unroll
                    for (int e = 0; e < bf.num_elements; e++) bf.x[e] = wmma::__float_to_tf32(bf.x[e]);
                    wmma::mma_sync(acc[j], af, bf, acc[j]);
                }
            }
            __syncthreads();
        }
        #pragma unroll
        for (int j = 0; j < 3; j++)
            wmma::store_matrix_sync(sh_k + mt * 16 * LDA + (ctB + j) * 16, acc[j], LDA, wmma::mem_row_major);
    }
    __syncthreads();

    // y = x + proj + proj_b  -> g_y (window reverse)
    for (int idx = tid; idx < 3072; idx += 512) {
        const int n = idx / 48, c4 = (idx - n * 48) * 4;
        const int iy = n >> 3, ix = n & 7;
        const size_t gp = ((size_t)((b * 64 + row0 + iy) * 64 + col0 + ix)) * C_ + c4;
        const float4 xv = *(const float4*)(x + gp);
        const float4 pb = *(const float4*)(projb + c4);
        const float* yt = sh_k + n * LDA + c4;
        float4 o4;
        o4.x = xv.x + yt[0] + pb.x;
        o4.y = xv.y + yt[1] + pb.y;
        o4.z = xv.z + yt[2] + pb.z;
        o4.w = xv.w + yt[3] + pb.w;
        *(float4*)(g_y + gp) = o4;
    }
}

// ---------------------------------------------------------------------------
// Kernel B: per-128-token tile  LN2 -> fc1 -> GELU -> fc2 -> +y
// grid = 1024, 512 threads, dynamic smem = 225792 B
// smem: a_s[128][196] | t_s[128][196] | w_s[32][196]
// ---------------------------------------------------------------------------
__global__ __launch_bounds__(512) void k_mlp(
    const float* __restrict__ n2g,  const float* __restrict__ n2b,
    const float* __restrict__ fc1w, const float* __restrict__ fc1b,
    const float* __restrict__ fc2w, const float* __restrict__ fc2b,
    float* __restrict__ out)
{
    extern __shared__ __align__(128) float smem[];
    float* a_s = smem;            // 128 * 196 = 25088
    float* t_s = smem + 25088;    // 128 * 196
    float* w_s = smem + 50176;    // 32  * 196
    const int tid = threadIdx.x, lane = tid & 31, wp = tid >> 5;
    const size_t p0 = (size_t)blockIdx.x * 128;

    // LN2: each warp handles 8 tokens
    #pragma unroll
    for (int ni = 0; ni < 8; ni++) {
        const int n = wp * 8 + ni;
        const float* yp = g_y + (p0 + n) * C_;
        float v[6]; float s = 0.f, s2 = 0.f;
        #pragma unroll
        for (int j = 0; j < 6; j++) { v[j] = yp[lane + 32 * j]; s += v[j]; s2 += v[j] * v[j]; }
        #pragma unroll
        for (int o = 16; o > 0; o >>= 1) {
            s  += __shfl_xor_sync(0xffffffffu, s,  o);
            s2 += __shfl_xor_sync(0xffffffffu, s2, o);
        }
        const float mean = s * (1.f / 192.f);
        const float rstd = rsqrtf(fmaxf(s2 * (1.f / 192.f) - mean * mean, 0.f) + 1e-5f);
        #pragma unroll
        for (int j = 0; j < 6; j++) {
            const int c = lane + 32 * j;
            a_s[n * LDA + c] = (v[j] - mean) * rstd * n2g[c] + n2b[c];
        }
    }
    __syncthreads();

    // tiling: 8 row tiles (M=128), 12 col tiles (N=192)
    const int mt  = wp >> 1;          // 8 row tiles, 2 warps each
    const int ctB = (wp & 1) * 6;     // 12 col tiles -> 6 per warp
    wmma::fragment<wmma::accumulator, 16, 16, 8, float> acc2[6];
    #pragma unroll
    for (int j = 0; j < 6; j++) wmma::fill_fragment(acc2[j], 0.f);

    // staging geometry: 32 rows x 192 cols, 3 float4 per thread
    const int sr  = (tid * 3) / 144 ? 0 : 0; // (dummy to keep structure simple)
    for (int hc = 0; hc < 4; hc++) {
        // ---- fc1 chunk: t = a @ W1[:, hc*192 : +192] ----
        wmma::fragment<wmma::accumulator, 16, 16, 8, float> acc1[6];
        #pragma unroll
        for (int j = 0; j < 6; j++) wmma::fill_fragment(acc1[j], 0.f);

        float4 pre[3];
        #pragma unroll
        for (int i = 0; i < 3; i++) {
            const int idx = tid + 512 * i;
            const int r = idx / 48, c4 = (idx - r * 48) * 4;
            pre[i] = *(const float4*)(fc1w + (size_t)r * HIDDEN + hc * 192 + c4);
        }
        for (int kc = 0; kc < 6; kc++) {
            const int k0 = kc * 32;
            #pragma unroll
            for (int i = 0; i < 3; i++) {
                const int idx = tid + 512 * i;
                const int r = idx / 48, c4 = (idx - r * 48) * 4;
                *(float4*)(w_s + r * LDA + c4) = pre[i];
            }
            __syncthreads();
            if (kc < 5) {
                #pragma unroll
                for (int i = 0; i < 3; i++) {
                    const int idx = tid + 512 * i;
                    const int r = idx / 48, c4 = (idx - r * 48) * 4;
                    pre[i] = *(const float4*)(fc1w + (size_t)(k0 + 32 + r) * HIDDEN + hc * 192 + c4);
                }
            }
            #pragma unroll
            for (int kk = 0; kk < 4; kk++) {
                wmma::fragment<wmma::matrix_a, 16, 16, 8, wmma::precision::tf32, wmma::row_major> af;
                wmma::load_matrix_sync(af, a_s + mt * 16 * LDA + k0 + kk * 8, LDA);
                #pragma unroll
                for (int e = 0; e < af.num_elements; e++) af.x[e] = wmma::__float_to_tf32(af.x[e]);
                #pragma unroll
                for (int j = 0; j < 6; j++) {
                    wmma::fragment<wmma::matrix_b, 16, 16, 8, wmma::precision::tf32, wmma::row_major> bf;
                    wmma::load_matrix_sync(bf, w_s + kk * 8 * LDA + (ctB + j) * 16, LDA);
                    #pragma unroll
                    for (int e = 0; e < bf.num_elements; e++) bf.x[e] = wmma::__float_to_tf32(bf.x[e]);
                    wmma::mma_sync(acc1[j], af, bf, acc1[j]);
                }
            }
            __syncthreads();
        }
        #pragma unroll
        for (int j = 0; j < 6; j++)
            wmma::store_matrix_sync(t_s + mt * 16 * LDA + (ctB + j) * 16, acc1[j], LDA, wmma::mem_row_major);
        __syncthreads();
        // GELU (exact erf) + fc1 bias
        for (int idx = tid; idx < 128 * 192; idx += 512) {
            const int n = idx / 192, c = idx - n * 192;
            const float vv = t_s[n * LDA + c] + fc1b[hc * 192 + c];
            t_s[n * LDA + c] = 0.5f * vv * (1.f + erff(vv * 0.7071067811865476f));
        }
        __syncthreads();
        // ---- fc2 partial: acc2 += t @ W2[hc*192 : +192, :] ----
        #pragma unroll
        for (int i = 0; i < 3; i++) {
            const int idx = tid + 512 * i;
            const int r = idx / 48, c4 = (idx - r * 48) * 4;
            pre[i] = *(const float4*)(fc2w + (size_t)(hc * 192 + r) * 192 + c4);
        }
        for (int kc = 0; kc < 6; kc++) {
            const int k0 = kc * 32;
            #pragma unroll
            for (int i = 0; i < 3; i++) {
                const int idx = tid + 512 * i;
                const int r = idx / 48, c4 = (idx - r * 48) * 4;
                *(float4*)(w_s + r * LDA + c4) = pre[i];
            }
            __syncthreads();
            if (kc < 5) {
                #pragma unroll
                for (int i = 0; i < 3; i++) {
                    const int idx = tid + 512 * i;
                    const int r = idx / 48, c4 = (idx - r * 48) * 4;
                    pre[i] = *(const float4*)(fc2w + (size_t)(hc * 192 + k0 + 32 + r) * 192 + c4);
                }
            }
            #pragma unroll
            for (int kk = 0; kk < 4; kk++) {
                wmma::fragment<wmma::matrix_a, 16, 16, 8, wmma::precision::tf32, wmma::row_major> af;
                wmma::load_matrix_sync(af, t_s + mt * 16 * LDA + k0 + kk * 8, LDA);
                #pragma unroll
                for (int e = 0; e < af.num_elements; e++) af.x[e] = wmma::__float_to_tf32(af.x[e]);
                #pragma unroll
                for (int j = 0; j < 6; j++) {
                    wmma::fragment<wmma::matrix_b, 16, 16, 8, wmma::precision::tf32, wmma::row_major> bf;
                    wmma::load_matrix_sync(bf, w_s + kk * 8 * LDA + (ctB + j) * 16, LDA);
                    #pragma unroll
                    for (int e = 0; e < bf.num_elements; e++) bf.x[e] = wmma::__float_to_tf32(bf.x[e]);
                    wmma::mma_sync(acc2[j], af, bf, acc2[j]);
                }
            }
            __syncthreads();
        }
    }
    #pragma unroll
    for (int j = 0; j < 6; j++)
        wmma::store_matrix_sync(t_s + mt * 16 * LDA + (ctB + j) * 16, acc2[j], LDA, wmma::mem_row_major);
    __syncthreads();

    // out = y + h2 + fc2_b
    for (int idx = tid; idx < 128 * 48; idx += 512) {
        const int n = idx / 48, c4 = (idx - n * 48) * 4;
        const size_t gp = (p0 + n) * C_ + c4;
        const float4 yv = *(const float4*)(g_y + gp);
        const float4 bb = *(const float4*)(fc2b + c4);
        const float* tt = t_s + n * LDA + c4;
        float4 o4;
        o4.x = yv.x + tt[0] + bb.x;
        o4.y = yv.y + tt[1] + bb.y;
        o4.z = yv.z + tt[2] + bb.z;
        o4.w = yv.w + tt[3] + bb.w;
        *(float4*)(out + gp) = o4;
    }
}

// ---------------------------------------------------------------------------
extern "C" void kernel_launch(void* const* d_in, const int* in_sizes, int n_in,
                              void* d_out, int out_size)
{
    const float* x     = (const float*)d_in[0];
    const float* qg    = (const float*)d_in[1];
    const float* n1g   = (const float*)d_in[2];
    const float* n1b   = (const float*)d_in[3];
    const float* qkvw  = (const float*)d_in[4];
    const float* qkvb  = (const float*)d_in[5];
    const float* rpb   = (const float*)d_in[6];
    const float* projw = (const float*)d_in[7];
    const float* projb = (const float*)d_in[8];
    const float* n2g   = (const float*)d_in[9];
    const float* n2b   = (const float*)d_in[10];
    const float* fc1w  = (const float*)d_in[11];
    const float* fc1b  = (const float*)d_in[12];
    const float* fc2w  = (const float*)d_in[13];
    const float* fc2b  = (const float*)d_in[14];
    float* out = (float*)d_out;

    cudaFuncSetAttribute(k_attn, cudaFuncAttributeMaxDynamicSharedMemorySize, 204800);
    cudaFuncSetAttribute(k_mlp,  cudaFuncAttributeMaxDynamicSharedMemorySize, 225792);

    k_attn<<<2048, 512, 204800>>>(x, qg, n1g, n1b, qkvw, qkvb, rpb, projw, projb);
    k_mlp <<<1024, 512, 225792>>>(n2g, n2b, fc1w, fc1b, fc2w, fc2b, out);
}

// round 7
// speedup vs baseline: 1.6690x; 1.6690x over previous
#include <cuda_runtime.h>
#include <cuda_bf16.h>
#include <mma.h>
#include <math.h>
#include <stdint.h>

using namespace nvcuda;

// Problem constants
#define C_     192
#define LDH    200          // bf16 tile row stride (elements): 192 + 8 pad
#define LDK    196          // fp32 tile row stride (K/V, scratch)
#define HIDDEN 768
#define NPIX   (32*64*64)   // 131072 tokens

// scratch for first residual output y = x + attn_out
__device__ float g_y[(size_t)NPIX * C_];

// store 4 consecutive bf16 from a float4 (8-byte aligned dst)
__device__ __forceinline__ void st_bf16x4(__nv_bfloat16* dst, float4 v) {
    __nv_bfloat162 lo = __floats2bfloat162_rn(v.x, v.y);
    __nv_bfloat162 hi = __floats2bfloat162_rn(v.z, v.w);
    uint2 u;
    u.x = *(uint32_t*)&lo;
    u.y = *(uint32_t*)&hi;
    *(uint2*)dst = u;
}

typedef wmma::fragment<wmma::matrix_a, 16, 16, 16, __nv_bfloat16, wmma::row_major> FragA;
typedef wmma::fragment<wmma::matrix_b, 16, 16, 16, __nv_bfloat16, wmma::row_major> FragB;
typedef wmma::fragment<wmma::accumulator, 16, 16, 16, float> FragC;

// ---------------------------------------------------------------------------
// Kernel A: per-window  LN1 -> qkv GEMM(bf16) -> attention(fp32) -> proj(bf16) -> +x
// grid = 2048 windows, 512 threads, dynamic smem = 179200 B
// layout (bytes):
//   [0      , 25600 ) sh_h  bf16 [64][200]   (LN out; later attn output o)
//   [25600  , 75776 ) sh_k  f32  [64][196]   (K; later proj result)
//   [75776  , 125952) sh_v  f32  [64][196]
//   [125952 , 175104) sh_wb bf16 weight staging  /  sh_q f32 12288 (q, attn phase)
//   [175104 , 179200) p_buf f32 [16][64]
// ---------------------------------------------------------------------------
__global__ __launch_bounds__(512) void k_attn(
    const float* __restrict__ x,     const float* __restrict__ qg,
    const float* __restrict__ n1g,   const float* __restrict__ n1b,
    const float* __restrict__ qkvw,  const float* __restrict__ qkvb,
    const float* __restrict__ rpb,
    const float* __restrict__ projw, const float* __restrict__ projb)
{
    extern __shared__ __align__(128) char sm[];
    __nv_bfloat16* sh_h  = (__nv_bfloat16*)sm;
    float*         sh_k  = (float*)(sm + 25600);
    float*         sh_v  = (float*)(sm + 75776);
    __nv_bfloat16* sh_wb = (__nv_bfloat16*)(sm + 125952);
    float*         sh_q  = (float*)(sm + 125952);
    float*         p_buf = (float*)(sm + 175104);

    const int w  = blockIdx.x;
    const int b  = w >> 6, wy = (w >> 3) & 7, wx = w & 7;
    const int tid = threadIdx.x, lane = tid & 31, wp = tid >> 5;
    const int row0 = wy * 8, col0 = wx * 8;

    // ---------------- LN1 (warp per token, 4 tokens/warp) -> bf16 ----------------
    #pragma unroll
    for (int ni = 0; ni < 4; ni++) {
        const int n = wp * 4 + ni;
        const float* xp = x + ((size_t)((b * 64 + row0 + (n >> 3)) * 64 + col0 + (n & 7))) * C_;
        float v[6]; float s = 0.f, s2 = 0.f;
        #pragma unroll
        for (int j = 0; j < 6; j++) { v[j] = xp[lane + 32 * j]; s += v[j]; s2 += v[j] * v[j]; }
        #pragma unroll
        for (int o = 16; o > 0; o >>= 1) {
            s  += __shfl_xor_sync(0xffffffffu, s,  o);
            s2 += __shfl_xor_sync(0xffffffffu, s2, o);
        }
        const float mean = s * (1.f / 192.f);
        const float rstd = rsqrtf(fmaxf(s2 * (1.f / 192.f) - mean * mean, 0.f) + 1e-5f);
        #pragma unroll
        for (int j = 0; j < 6; j++) {
            const int c = lane + 32 * j;
            sh_h[n * LDH + c] = __float2bfloat16((v[j] - mean) * rstd * n1g[c] + n1b[c]);
        }
    }
    __syncthreads();

    // ---------------- QKV GEMM: [64x192] @ [192x384] (bf16 wmma) ----------------
    {
        const int ctBase = (wp >> 1) * 3;   // 24 col tiles -> 3 per warp-pair
        const int mt0    = (wp & 1) * 2;    // 4 row tiles -> 2 per warp
        FragC acc[6];
        #pragma unroll
        for (int i = 0; i < 6; i++) wmma::fill_fragment(acc[i], 0.f);

        // prologue prefetch of kc=0 weight tile (32x384 f32 -> 6 float4/thread)
        float4 pre[6];
        #pragma unroll
        for (int i = 0; i < 6; i++) {
            const int idx = tid + 512 * i;
            const int r = idx / 96, c4 = (idx - r * 96) * 4;
            pre[i] = *(const float4*)(qkvw + r * 384 + c4);
        }

        for (int kc = 0; kc < 6; kc++) {
            const int k0 = kc * 32;
            // commit prefetched tile -> sh_wb bf16, row stride 392
            #pragma unroll
            for (int i = 0; i < 6; i++) {
                const int idx = tid + 512 * i;
                const int r = idx / 96, c4 = (idx - r * 96) * 4;
                st_bf16x4(sh_wb + r * 392 + c4, pre[i]);
            }
            __syncthreads();
            if (kc < 5) {
                #pragma unroll
                for (int i = 0; i < 6; i++) {
                    const int idx = tid + 512 * i;
                    const int r = idx / 96, c4 = (idx - r * 96) * 4;
                    pre[i] = *(const float4*)(qkvw + (k0 + 32 + r) * 384 + c4);
                }
            }
            #pragma unroll
            for (int kk = 0; kk < 2; kk++) {
                FragA af[2];
                #pragma unroll
                for (int i = 0; i < 2; i++)
                    wmma::load_matrix_sync(af[i], sh_h + (mt0 + i) * 16 * LDH + k0 + kk * 16, LDH);
                #pragma unroll
                for (int j = 0; j < 3; j++) {
                    FragB bf;
                    wmma::load_matrix_sync(bf, sh_wb + kk * 16 * 392 + (ctBase + j) * 16, 392);
                    #pragma unroll
                    for (int i = 0; i < 2; i++) wmma::mma_sync(acc[i * 3 + j], af[i], bf, acc[i * 3 + j]);
                }
            }
            __syncthreads();
        }
        #pragma unroll
        for (int i = 0; i < 2; i++)
            #pragma unroll
            for (int j = 0; j < 3; j++) {
                const int cg = (ctBase + j) * 16;
                float* dst = (cg < 192) ? (sh_k + (mt0 + i) * 16 * LDK + cg)
                                        : (sh_v + (mt0 + i) * 16 * LDK + (cg - 192));
                wmma::store_matrix_sync(dst, acc[i * 3 + j], LDK, wmma::mem_row_major);
            }
    }
    __syncthreads();

    // qkv bias + stage q*scale into sh_q ([head][n][d], compact)
    for (int idx = tid; idx < 3072; idx += 512) {
        const int n = idx / 48, c4 = (idx - n * 48) * 4;
        const float4 bk = *(const float4*)(qkvb + c4);
        const float4 bv = *(const float4*)(qkvb + 192 + c4);
        float* pk = sh_k + n * LDK + c4;
        float* pv = sh_v + n * LDK + c4;
        pk[0] += bk.x; pk[1] += bk.y; pk[2] += bk.z; pk[3] += bk.w;
        pv[0] += bv.x; pv[1] += bv.y; pv[2] += bv.z; pv[3] += bv.w;
    }
    for (int idx = tid; idx < 12288; idx += 512) {
        const int d = idx & 31, n = (idx >> 5) & 63, head = idx >> 11;
        sh_q[idx] = qg[(((size_t)b * 64 + n) * 6 + head) * 32 + d] * 0.17677669529663688f; // 1/sqrt(32)
    }
    __syncthreads();

    // ---------------- attention: 384 (head,row) tasks over 16 warps (fp32) ----------------
    for (int it = 0; it < 24; it++) {
        const int t = wp + (it << 4);
        const int head = t >> 6, n = t & 63;
        const int hb = head << 5;
        const float4* q4 = (const float4*)(sh_q + (head << 11) + (n << 5));
        const int iy = n >> 3, ix = n & 7;
        float s01[2];
        #pragma unroll
        for (int half = 0; half < 2; half++) {
            const int m = lane + half * 32;
            const float4* kr = (const float4*)(sh_k + m * LDK + hb);
            float a0 = 0.f;
            #pragma unroll
            for (int d4 = 0; d4 < 8; d4++) {
                const float4 kk4 = kr[d4]; const float4 qq4 = q4[d4];
                a0 += kk4.x * qq4.x + kk4.y * qq4.y + kk4.z * qq4.z + kk4.w * qq4.w;
            }
            const int jy = m >> 3, jx = m & 7;
            s01[half] = a0 + rpb[((iy - jy + 7) * 15 + (ix - jx + 7)) * 6 + head];
        }
        float mx = fmaxf(s01[0], s01[1]);
        #pragma unroll
        for (int o = 16; o > 0; o >>= 1) mx = fmaxf(mx, __shfl_xor_sync(0xffffffffu, mx, o));
        const float e0 = __expf(s01[0] - mx), e1 = __expf(s01[1] - mx);
        float sm_ = e0 + e1;
        #pragma unroll
        for (int o = 16; o > 0; o >>= 1) sm_ += __shfl_xor_sync(0xffffffffu, sm_, o);
        const float inv = 1.f / sm_;
        p_buf[(wp << 6) + lane]      = e0 * inv;
        p_buf[(wp << 6) + lane + 32] = e1 * inv;
        __syncwarp();
        float oacc = 0.f;
        #pragma unroll 8
        for (int m = 0; m < 64; m++) oacc += p_buf[(wp << 6) + m] * sh_v[m * LDK + hb + lane];
        sh_h[n * LDH + hb + lane] = __float2bfloat16(oacc);   // o (bf16) overwrites h
        __syncwarp();
    }
    __syncthreads();

    // ---------------- proj: o[64x192] @ proj_w[192x192] (bf16 wmma) ----------------
    {
        const int mt  = wp >> 2;          // 4 row tiles
        const int ctB = (wp & 3) * 3;     // 12 col tiles -> 3/warp
        FragC acc[3];
        #pragma unroll
        for (int j = 0; j < 3; j++) wmma::fill_fragment(acc[j], 0.f);

        float4 pre[6];
        #pragma unroll
        for (int i = 0; i < 6; i++) {
            const int idx = tid + 512 * i;
            const int r = idx / 48, c4 = (idx - r * 48) * 4;
            pre[i] = *(const float4*)(projw + r * 192 + c4);
        }

        for (int kc = 0; kc < 3; kc++) {
            const int k0 = kc * 64;
            #pragma unroll
            for (int i = 0; i < 6; i++) {
                const int idx = tid + 512 * i;
                const int r = idx / 48, c4 = (idx - r * 48) * 4;
                st_bf16x4(sh_wb + r * LDH + c4, pre[i]);
            }
            __syncthreads();
            if (kc < 2) {
                #pragma unroll
                for (int i = 0; i < 6; i++) {
                    const int idx = tid + 512 * i;
                    const int r = idx / 48, c4 = (idx - r * 48) * 4;
                    pre[i] = *(const float4*)(projw + (k0 + 64 + r) * 192 + c4);
                }
            }
            #pragma unroll
            for (int kk = 0; kk < 4; kk++) {
                FragA af;
                wmma::load_matrix_sync(af, sh_h + mt * 16 * LDH + k0 + kk * 16, LDH);
                #pragma unroll
                for (int j = 0; j < 3; j++) {
                    FragB bf;
                    wmma::load_matrix_sync(bf, sh_wb + kk * 16 * LDH + (ctB + j) * 16, LDH);
                    wmma::mma_sync(acc[j], af, bf, acc[j]);
                }
            }
            __syncthreads();
        }
        #pragma unroll
        for (int j = 0; j < 3; j++)
            wmma::store_matrix_sync(sh_k + mt * 16 * LDK + (ctB + j) * 16, acc[j], LDK, wmma::mem_row_major);
    }
    __syncthreads();

    // y = x + proj + proj_b  -> g_y (window reverse)
    for (int idx = tid; idx < 3072; idx += 512) {
        const int n = idx / 48, c4 = (idx - n * 48) * 4;
        const int iy = n >> 3, ix = n & 7;
        const size_t gp = ((size_t)((b * 64 + row0 + iy) * 64 + col0 + ix)) * C_ + c4;
        const float4 xv = *(const float4*)(x + gp);
        const float4 pb = *(const float4*)(projb + c4);
        const float* yt = sh_k + n * LDK + c4;
        float4 o4;
        o4.x = xv.x + yt[0] + pb.x;
        o4.y = xv.y + yt[1] + pb.y;
        o4.z = xv.z + yt[2] + pb.z;
        o4.w = xv.w + yt[3] + pb.w;
        *(float4*)(g_y + gp) = o4;
    }
}

// ---------------------------------------------------------------------------
// Kernel B: per-128-token tile  LN2 -> fc1(bf16) -> GELU -> fc2(bf16) -> +y
// grid = 1024, 512 threads, dynamic smem = 215552 B
// layout (bytes):
//   [0      , 51200 ) a_s bf16 [128][200]
//   [51200  , 102400) t_s bf16 [128][200]
//   [102400 , 115200) w_s bf16 [32][200]
//   [115200 , 215552) t_f f32  [128][196]
// ---------------------------------------------------------------------------
__global__ __launch_bounds__(512) void k_mlp(
    const float* __restrict__ n2g,  const float* __restrict__ n2b,
    const float* __restrict__ fc1w, const float* __restrict__ fc1b,
    const float* __restrict__ fc2w, const float* __restrict__ fc2b,
    float* __restrict__ out)
{
    extern __shared__ __align__(128) char sm[];
    __nv_bfloat16* a_s = (__nv_bfloat16*)sm;
    __nv_bfloat16* t_s = (__nv_bfloat16*)(sm + 51200);
    __nv_bfloat16* w_s = (__nv_bfloat16*)(sm + 102400);
    float*         t_f = (float*)(sm + 115200);
    const int tid = threadIdx.x, lane = tid & 31, wp = tid >> 5;
    const size_t p0 = (size_t)blockIdx.x * 128;

    // LN2: each warp handles 8 tokens -> bf16
    #pragma unroll
    for (int ni = 0; ni < 8; ni++) {
        const int n = wp * 8 + ni;
        const float* yp = g_y + (p0 + n) * C_;
        float v[6]; float s = 0.f, s2 = 0.f;
        #pragma unroll
        for (int j = 0; j < 6; j++) { v[j] = yp[lane + 32 * j]; s += v[j]; s2 += v[j] * v[j]; }
        #pragma unroll
        for (int o = 16; o > 0; o >>= 1) {
            s  += __shfl_xor_sync(0xffffffffu, s,  o);
            s2 += __shfl_xor_sync(0xffffffffu, s2, o);
        }
        const float mean = s * (1.f / 192.f);
        const float rstd = rsqrtf(fmaxf(s2 * (1.f / 192.f) - mean * mean, 0.f) + 1e-5f);
        #pragma unroll
        for (int j = 0; j < 6; j++) {
            const int c = lane + 32 * j;
            a_s[n * LDH + c] = __float2bfloat16((v[j] - mean) * rstd * n2g[c] + n2b[c]);
        }
    }
    __syncthreads();

    // tiling: 8 row tiles (M=128), 12 col tiles (N=192)
    const int mt  = wp >> 1;          // 8 row tiles, 2 warps each
    const int ctB = (wp & 1) * 6;     // 12 col tiles -> 6 per warp
    FragC acc2[6];
    #pragma unroll
    for (int j = 0; j < 6; j++) wmma::fill_fragment(acc2[j], 0.f);

    for (int hc = 0; hc < 4; hc++) {
        // ---- fc1 chunk: t = a @ W1[:, hc*192 : +192] ----
        FragC acc1[6];
        #pragma unroll
        for (int j = 0; j < 6; j++) wmma::fill_fragment(acc1[j], 0.f);

        float4 pre[3];
        #pragma unroll
        for (int i = 0; i < 3; i++) {
            const int idx = tid + 512 * i;
            const int r = idx / 48, c4 = (idx - r * 48) * 4;
            pre[i] = *(const float4*)(fc1w + (size_t)r * HIDDEN + hc * 192 + c4);
        }
        for (int kc = 0; kc < 6; kc++) {
            const int k0 = kc * 32;
            #pragma unroll
            for (int i = 0; i < 3; i++) {
                const int idx = tid + 512 * i;
                const int r = idx / 48, c4 = (idx - r * 48) * 4;
                st_bf16x4(w_s + r * LDH + c4, pre[i]);
            }
            __syncthreads();
            if (kc < 5) {
                #pragma unroll
                for (int i = 0; i < 3; i++) {
                    const int idx = tid + 512 * i;
                    const int r = idx / 48, c4 = (idx - r * 48) * 4;
                    pre[i] = *(const float4*)(fc1w + (size_t)(k0 + 32 + r) * HIDDEN + hc * 192 + c4);
                }
            }
            #pragma unroll
            for (int kk = 0; kk < 2; kk++) {
                FragA af;
                wmma::load_matrix_sync(af, a_s + mt * 16 * LDH + k0 + kk * 16, LDH);
                #pragma unroll
                for (int j = 0; j < 6; j++) {
                    FragB bf;
                    wmma::load_matrix_sync(bf, w_s + kk * 16 * LDH + (ctB + j) * 16, LDH);
                    wmma::mma_sync(acc1[j], af, bf, acc1[j]);
                }
            }
            __syncthreads();
        }
        #pragma unroll
        for (int j = 0; j < 6; j++)
            wmma::store_matrix_sync(t_f + mt * 16 * LDK + (ctB + j) * 16, acc1[j], LDK, wmma::mem_row_major);
        __syncthreads();
        // GELU (exact erf) + fc1 bias, fp32 -> bf16 pairs
        for (int idx = tid; idx < 128 * 96; idx += 512) {
            const int n = idx / 96, c2 = (idx - n * 96) * 2;
            float v0 = t_f[n * LDK + c2]     + fc1b[hc * 192 + c2];
            float v1 = t_f[n * LDK + c2 + 1] + fc1b[hc * 192 + c2 + 1];
            v0 = 0.5f * v0 * (1.f + erff(v0 * 0.7071067811865476f));
            v1 = 0.5f * v1 * (1.f + erff(v1 * 0.7071067811865476f));
            *(__nv_bfloat162*)(t_s + n * LDH + c2) = __floats2bfloat162_rn(v0, v1);
        }
        __syncthreads();
        // ---- fc2 partial: acc2 += t @ W2[hc*192 : +192, :] ----
        #pragma unroll
        for (int i = 0; i < 3; i++) {
            const int idx = tid + 512 * i;
            const int r = idx / 48, c4 = (idx - r * 48) * 4;
            pre[i] = *(const float4*)(fc2w + (size_t)(hc * 192 + r) * 192 + c4);
        }
        for (int kc = 0; kc < 6; kc++) {
            const int k0 = kc * 32;
            #pragma unroll
            for (int i = 0; i < 3; i++) {
                const int idx = tid + 512 * i;
                const int r = idx / 48, c4 = (idx - r * 48) * 4;
                st_bf16x4(w_s + r * LDH + c4, pre[i]);
            }
            __syncthreads();
            if (kc < 5) {
                #pragma unroll
                for (int i = 0; i < 3; i++) {
                    const int idx = tid + 512 * i;
                    const int r = idx / 48, c4 = (idx - r * 48) * 4;
                    pre[i] = *(const float4*)(fc2w + (size_t)(hc * 192 + k0 + 32 + r) * 192 + c4);
                }
            }
            #pragma unroll
            for (int kk = 0; kk < 2; kk++) {
                FragA af;
                wmma::load_matrix_sync(af, t_s + mt * 16 * LDH + k0 + kk * 16, LDH);
                #pragma unroll
                for (int j = 0; j < 6; j++) {
                    FragB bf;
                    wmma::load_matrix_sync(bf, w_s + kk * 16 * LDH + (ctB + j) * 16, LDH);
                    wmma::mma_sync(acc2[j], af, bf, acc2[j]);
                }
            }
            __syncthreads();
        }
    }
    #pragma unroll
    for (int j = 0; j < 6; j++)
        wmma::store_matrix_sync(t_f + mt * 16 * LDK + (ctB + j) * 16, acc2[j], LDK, wmma::mem_row_major);
    __syncthreads();

    // out = y + h2 + fc2_b
    for (int idx = tid; idx < 128 * 48; idx += 512) {
        const int n = idx / 48, c4 = (idx - n * 48) * 4;
        const size_t gp = (p0 + n) * C_ + c4;
        const float4 yv = *(const float4*)(g_y + gp);
        const float4 bb = *(const float4*)(fc2b + c4);
        const float* tt = t_f + n * LDK + c4;
        float4 o4;
        o4.x = yv.x + tt[0] + bb.x;
        o4.y = yv.y + tt[1] + bb.y;
        o4.z = yv.z + tt[2] + bb.z;
        o4.w = yv.w + tt[3] + bb.w;
        *(float4*)(out + gp) = o4;
    }
}

// ---------------------------------------------------------------------------
extern "C" void kernel_launch(void* const* d_in, const int* in_sizes, int n_in,
                              void* d_out, int out_size)
{
    const float* x     = (const float*)d_in[0];
    const float* qg    = (const float*)d_in[1];
    const float* n1g   = (const float*)d_in[2];
    const float* n1b   = (const float*)d_in[3];
    const float* qkvw  = (const float*)d_in[4];
    const float* qkvb  = (const float*)d_in[5];
    const float* rpb   = (const float*)d_in[6];
    const float* projw = (const float*)d_in[7];
    const float* projb = (const float*)d_in[8];
    const float* n2g   = (const float*)d_in[9];
    const float* n2b   = (const float*)d_in[10];
    const float* fc1w  = (const float*)d_in[11];
    const float* fc1b  = (const float*)d_in[12];
    const float* fc2w  = (const float*)d_in[13];
    const float* fc2b  = (const float*)d_in[14];
    float* out = (float*)d_out;

    cudaFuncSetAttribute(k_attn, cudaFuncAttributeMaxDynamicSharedMemorySize, 179200);
    cudaFuncSetAttribute(k_mlp,  cudaFuncAttributeMaxDynamicSharedMemorySize, 215552);

    k_attn<<<2048, 512, 179200>>>(x, qg, n1g, n1b, qkvw, qkvb, rpb, projw, projb);
    k_mlp <<<1024, 512, 215552>>>(n2g, n2b, fc1w, fc1b, fc2w, fc2b, out);
}

// round 8
// speedup vs baseline: 2.2754x; 1.3633x over previous
#include <cuda_runtime.h>
#include <cuda_bf16.h>
#include <mma.h>
#include <math.h>
#include <stdint.h>

using namespace nvcuda;

#define C_     192
#define LDH    200          // bf16 tile row stride (elements)
#define LDK    196          // fp32 scratch row stride
#define HIDDEN 768
#define NPIX   (32*64*64)

__device__ float g_y[(size_t)NPIX * C_];

__device__ __forceinline__ void st_bf16x4(__nv_bfloat16* dst, float4 v) {
    __nv_bfloat162 lo = __floats2bfloat162_rn(v.x, v.y);
    __nv_bfloat162 hi = __floats2bfloat162_rn(v.z, v.w);
    uint2 u; u.x = *(uint32_t*)&lo; u.y = *(uint32_t*)&hi;
    *(uint2*)dst = u;
}

typedef wmma::fragment<wmma::matrix_a, 16, 16, 16, __nv_bfloat16, wmma::row_major> FragA;
typedef wmma::fragment<wmma::matrix_b, 16, 16, 16, __nv_bfloat16, wmma::row_major> FragB;
typedef wmma::fragment<wmma::matrix_b, 16, 16, 16, __nv_bfloat16, wmma::col_major> FragBT;
typedef wmma::fragment<wmma::accumulator, 16, 16, 16, float> FragC;

// ---------------------------------------------------------------------------
// Kernel A: per-window  LN1 -> qkv(bf16 wmma) -> attention (wmma S,PV; fp32 softmax)
//           -> proj(bf16 wmma) -> +x
// grid = 2048, 512 threads, dynamic smem = 199680 B
//   [0     ,  25600) sh_h bf16 [64][200]   (LN out; later o)
//   [25600 ,  51200) kb   bf16 [64][200]
//   [51200 ,  76800) vb   bf16 [64][200]
//   [76800 , 101376) qb   bf16 [6][64][32]
//   [101376, 199680) big: staging(double) / qkv_f f32[64][384] / S f32[6][64][64]
//                         / P bf16 in-place / o_f f32[64][196] / proj_f f32[64][196]
// ---------------------------------------------------------------------------
__global__ __launch_bounds__(512) void k_attn(
    const float* __restrict__ x,     const float* __restrict__ qg,
    const float* __restrict__ n1g,   const float* __restrict__ n1b,
    const float* __restrict__ qkvw,  const float* __restrict__ qkvb,
    const float* __restrict__ rpb,
    const float* __restrict__ projw, const float* __restrict__ projb)
{
    extern __shared__ __align__(128) char sm[];
    __nv_bfloat16* sh_h = (__nv_bfloat16*)sm;
    __nv_bfloat16* kb   = (__nv_bfloat16*)(sm + 25600);
    __nv_bfloat16* vb   = (__nv_bfloat16*)(sm + 51200);
    __nv_bfloat16* qb   = (__nv_bfloat16*)(sm + 76800);
    char* big = sm + 101376;

    const int w  = blockIdx.x;
    const int b  = w >> 6, wy = (w >> 3) & 7, wx = w & 7;
    const int tid = threadIdx.x, lane = tid & 31, wp = tid >> 5;
    const int row0 = wy * 8, col0 = wx * 8;

    // ---------------- LN1 -> bf16 ----------------
    #pragma unroll
    for (int ni = 0; ni < 4; ni++) {
        const int n = wp * 4 + ni;
        const float* xp = x + ((size_t)((b * 64 + row0 + (n >> 3)) * 64 + col0 + (n & 7))) * C_;
        float v[6]; float s = 0.f, s2 = 0.f;
        #pragma unroll
        for (int j = 0; j < 6; j++) { v[j] = xp[lane + 32 * j]; s += v[j]; s2 += v[j] * v[j]; }
        #pragma unroll
        for (int o = 16; o > 0; o >>= 1) {
            s  += __shfl_xor_sync(0xffffffffu, s,  o);
            s2 += __shfl_xor_sync(0xffffffffu, s2, o);
        }
        const float mean = s * (1.f / 192.f);
        const float rstd = rsqrtf(fmaxf(s2 * (1.f / 192.f) - mean * mean, 0.f) + 1e-5f);
        #pragma unroll
        for (int j = 0; j < 6; j++) {
            const int c = lane + 32 * j;
            sh_h[n * LDH + c] = __float2bfloat16((v[j] - mean) * rstd * n1g[c] + n1b[c]);
        }
    }
    __syncthreads();

    // ---------------- QKV GEMM [64x192]@[192x384], double-buffered staging ----------------
    {
        const int ctBase = (wp >> 1) * 3;
        const int mt0    = (wp & 1) * 2;
        FragC acc[6];
        #pragma unroll
        for (int i = 0; i < 6; i++) wmma::fill_fragment(acc[i], 0.f);

        float4 pre[6];
        #pragma unroll
        for (int i = 0; i < 6; i++) {
            const int idx = tid + 512 * i;
            const int r = idx / 96, c4 = (idx - r * 96) * 4;
            pre[i] = *(const float4*)(qkvw + r * 384 + c4);
        }
        for (int kc = 0; kc < 6; kc++) {
            const int k0 = kc * 32;
            __nv_bfloat16* wbuf = (__nv_bfloat16*)(big + (kc & 1) * 25088);
            #pragma unroll
            for (int i = 0; i < 6; i++) {
                const int idx = tid + 512 * i;
                const int r = idx / 96, c4 = (idx - r * 96) * 4;
                st_bf16x4(wbuf + r * 392 + c4, pre[i]);
            }
            if (kc < 5) {
                #pragma unroll
                for (int i = 0; i < 6; i++) {
                    const int idx = tid + 512 * i;
                    const int r = idx / 96, c4 = (idx - r * 96) * 4;
                    pre[i] = *(const float4*)(qkvw + (k0 + 32 + r) * 384 + c4);
                }
            }
            __syncthreads();
            #pragma unroll
            for (int kk = 0; kk < 2; kk++) {
                FragA af[2];
                #pragma unroll
                for (int i = 0; i < 2; i++)
                    wmma::load_matrix_sync(af[i], sh_h + (mt0 + i) * 16 * LDH + k0 + kk * 16, LDH);
                #pragma unroll
                for (int j = 0; j < 3; j++) {
                    FragB bf;
                    wmma::load_matrix_sync(bf, wbuf + kk * 16 * 392 + (ctBase + j) * 16, 392);
                    #pragma unroll
                    for (int i = 0; i < 2; i++) wmma::mma_sync(acc[i * 3 + j], af[i], bf, acc[i * 3 + j]);
                }
            }
        }
        __syncthreads();           // all mma done before overwriting staging with result
        float* qkv_f = (float*)big;
        #pragma unroll
        for (int i = 0; i < 2; i++)
            #pragma unroll
            for (int j = 0; j < 3; j++)
                wmma::store_matrix_sync(qkv_f + (mt0 + i) * 16 * 384 + (ctBase + j) * 16,
                                        acc[i * 3 + j], 384, wmma::mem_row_major);
    }
    __syncthreads();

    // ---------------- convert K,V (+bias) -> bf16; q*scale -> bf16 ----------------
    {
        float* qkv_f = (float*)big;
        for (int idx = tid; idx < 64 * 96; idx += 512) {
            const int n = idx / 96, c2 = (idx - n * 96) * 2;
            float k0v = qkv_f[n * 384 + c2]       + qkvb[c2];
            float k1v = qkv_f[n * 384 + c2 + 1]   + qkvb[c2 + 1];
            *(__nv_bfloat162*)(kb + n * LDH + c2) = __floats2bfloat162_rn(k0v, k1v);
            float v0v = qkv_f[n * 384 + 192 + c2]     + qkvb[192 + c2];
            float v1v = qkv_f[n * 384 + 192 + c2 + 1] + qkvb[192 + c2 + 1];
            *(__nv_bfloat162*)(vb + n * LDH + c2) = __floats2bfloat162_rn(v0v, v1v);
        }
        for (int idx = tid; idx < 12288; idx += 512) {
            const int d = idx & 31, n = (idx >> 5) & 63, h = idx >> 11;
            qb[h * 2048 + n * 32 + d] =
                __float2bfloat16(qg[(((size_t)b * 64 + n) * 6 + h) * 32 + d] * 0.17677669529663688f);
        }
    }
    __syncthreads();

    // ---------------- S = Q K^T (96 tiles, 6 per warp) ----------------
    {
        float* s_f = (float*)big;
        #pragma unroll
        for (int j = 0; j < 6; j++) {
            const int t = wp + (j << 4);
            const int head = t >> 4, sub = t & 15, mi = sub >> 2, ni = sub & 3;
            FragC acc;
            wmma::fill_fragment(acc, 0.f);
            #pragma unroll
            for (int kk = 0; kk < 2; kk++) {
                FragA af;
                wmma::load_matrix_sync(af, qb + head * 2048 + mi * 16 * 32 + kk * 16, 32);
                FragBT bf;
                wmma::load_matrix_sync(bf, kb + ni * 16 * LDH + head * 32 + kk * 16, LDH);
                wmma::mma_sync(acc, af, bf, acc);
            }
            wmma::store_matrix_sync(s_f + head * 4096 + mi * 16 * 64 + ni * 16, acc, 64,
                                    wmma::mem_row_major);
        }
    }
    __syncthreads();

    // ---------------- softmax rows (fp32), write P bf16 in place ----------------
    {
        float* s_f = (float*)big;
        #pragma unroll 4
        for (int it = 0; it < 24; it++) {
            const int t = wp + (it << 4);
            const int head = t >> 6, i = t & 63;
            const int iy = i >> 3, ix = i & 7;
            const int j0 = lane * 2;
            float s0 = s_f[head * 4096 + i * 64 + j0];
            float s1 = s_f[head * 4096 + i * 64 + j0 + 1];
            const int jy0 = j0 >> 3,     jx0 = j0 & 7;
            const int jy1 = (j0 + 1) >> 3, jx1 = (j0 + 1) & 7;
            s0 += rpb[((iy - jy0 + 7) * 15 + (ix - jx0 + 7)) * 6 + head];
            s1 += rpb[((iy - jy1 + 7) * 15 + (ix - jx1 + 7)) * 6 + head];
            float mx = fmaxf(s0, s1);
            #pragma unroll
            for (int o = 16; o > 0; o >>= 1) mx = fmaxf(mx, __shfl_xor_sync(0xffffffffu, mx, o));
            const float e0 = __expf(s0 - mx), e1 = __expf(s1 - mx);
            float sum = e0 + e1;
            #pragma unroll
            for (int o = 16; o > 0; o >>= 1) sum += __shfl_xor_sync(0xffffffffu, sum, o);
            const float inv = 1.f / sum;
            __nv_bfloat16* pr = (__nv_bfloat16*)(s_f + head * 4096 + i * 64);
            *(__nv_bfloat162*)(pr + j0) = __floats2bfloat162_rn(e0 * inv, e1 * inv);
        }
    }
    __syncthreads();

    // ---------------- O = P V (48 tiles, 3 per warp) ----------------
    {
        __nv_bfloat16* pb = (__nv_bfloat16*)big;
        FragC acc[3];
        int hh[3], mm[3], nn[3];
        #pragma unroll
        for (int j = 0; j < 3; j++) {
            const int t = wp + (j << 4);
            hh[j] = t >> 3; mm[j] = (t & 7) >> 1; nn[j] = t & 1;
            wmma::fill_fragment(acc[j], 0.f);
            #pragma unroll
            for (int kk = 0; kk < 4; kk++) {
                FragA af;
                wmma::load_matrix_sync(af, pb + hh[j] * 8192 + mm[j] * 16 * 128 + kk * 16, 128);
                FragB bf;
                wmma::load_matrix_sync(bf, vb + kk * 16 * LDH + hh[j] * 32 + nn[j] * 16, LDH);
                wmma::mma_sync(acc[j], af, bf, acc[j]);
            }
        }
        __syncthreads();           // all P reads done before overwriting with o
        float* o_f = (float*)big;
        #pragma unroll
        for (int j = 0; j < 3; j++)
            wmma::store_matrix_sync(o_f + mm[j] * 16 * LDK + hh[j] * 32 + nn[j] * 16, acc[j], LDK,
                                    wmma::mem_row_major);
    }
    __syncthreads();

    // ---------------- convert o -> sh_h bf16 ----------------
    {
        float* o_f = (float*)big;
        for (int idx = tid; idx < 64 * 96; idx += 512) {
            const int n = idx / 96, c2 = (idx - n * 96) * 2;
            *(__nv_bfloat162*)(sh_h + n * LDH + c2) =
                __floats2bfloat162_rn(o_f[n * LDK + c2], o_f[n * LDK + c2 + 1]);
        }
    }
    __syncthreads();

    // ---------------- proj [64x192]@[192x192], double-buffered ----------------
    {
        const int mt  = wp >> 2;
        const int ctB = (wp & 3) * 3;
        FragC acc[3];
        #pragma unroll
        for (int j = 0; j < 3; j++) wmma::fill_fragment(acc[j], 0.f);

        float4 pre[6];
        #pragma unroll
        for (int i = 0; i < 6; i++) {
            const int idx = tid + 512 * i;
            const int r = idx / 48, c4 = (idx - r * 48) * 4;
            pre[i] = *(const float4*)(projw + r * 192 + c4);
        }
        for (int kc = 0; kc < 3; kc++) {
            const int k0 = kc * 64;
            __nv_bfloat16* wbuf = (__nv_bfloat16*)(big + (kc & 1) * 25600);
            #pragma unroll
            for (int i = 0; i < 6; i++) {
                const int idx = tid + 512 * i;
                const int r = idx / 48, c4 = (idx - r * 48) * 4;
                st_bf16x4(wbuf + r * LDH + c4, pre[i]);
            }
            if (kc < 2) {
                #pragma unroll
                for (int i = 0; i < 6; i++) {
                    const int idx = tid + 512 * i;
                    const int r = idx / 48, c4 = (idx - r * 48) * 4;
                    pre[i] = *(const float4*)(projw + (k0 + 64 + r) * 192 + c4);
                }
            }
            __syncthreads();
            #pragma unroll
            for (int kk = 0; kk < 4; kk++) {
                FragA af;
                wmma::load_matrix_sync(af, sh_h + mt * 16 * LDH + k0 + kk * 16, LDH);
                #pragma unroll
                for (int j = 0; j < 3; j++) {
                    FragB bf;
                    wmma::load_matrix_sync(bf, wbuf + kk * 16 * LDH + (ctB + j) * 16, LDH);
                    wmma::mma_sync(acc[j], af, bf, acc[j]);
                }
            }
        }
        __syncthreads();
        float* proj_f = (float*)big;
        #pragma unroll
        for (int j = 0; j < 3; j++)
            wmma::store_matrix_sync(proj_f + mt * 16 * LDK + (ctB + j) * 16, acc[j], LDK,
                                    wmma::mem_row_major);
    }
    __syncthreads();

    // ---------------- y = x + proj + proj_b -> g_y ----------------
    {
        float* proj_f = (float*)big;
        for (int idx = tid; idx < 3072; idx += 512) {
            const int n = idx / 48, c4 = (idx - n * 48) * 4;
            const int iy = n >> 3, ix = n & 7;
            const size_t gp = ((size_t)((b * 64 + row0 + iy) * 64 + col0 + ix)) * C_ + c4;
            const float4 xv = *(const float4*)(x + gp);
            const float4 pb4 = *(const float4*)(projb + c4);
            const float* yt = proj_f + n * LDK + c4;
            float4 o4;
            o4.x = xv.x + yt[0] + pb4.x;
            o4.y = xv.y + yt[1] + pb4.y;
            o4.z = xv.z + yt[2] + pb4.z;
            o4.w = xv.w + yt[3] + pb4.w;
            *(float4*)(g_y + gp) = o4;
        }
    }
}

// ---------------------------------------------------------------------------
// Kernel B: per-128-token tile  LN2 -> fc1 -> GELU -> fc2 -> +y
// grid = 1024, 512 threads, dynamic smem = 228352 B
//   a_s bf16 [128][200] @0        (51200)
//   t_s bf16 [128][200] @51200    (51200)
//   w_s bf16 2x[32][200] @102400  (25600)
//   t_f f32  [128][196] @128000   (100352)
// ---------------------------------------------------------------------------
__global__ __launch_bounds__(512) void k_mlp(
    const float* __restrict__ n2g,  const float* __restrict__ n2b,
    const float* __restrict__ fc1w, const float* __restrict__ fc1b,
    const float* __restrict__ fc2w, const float* __restrict__ fc2b,
    float* __restrict__ out)
{
    extern __shared__ __align__(128) char sm[];
    __nv_bfloat16* a_s = (__nv_bfloat16*)sm;
    __nv_bfloat16* t_s = (__nv_bfloat16*)(sm + 51200);
    __nv_bfloat16* w_s = (__nv_bfloat16*)(sm + 102400);
    float*         t_f = (float*)(sm + 128000);
    const int tid = threadIdx.x, lane = tid & 31, wp = tid >> 5;
    const size_t p0 = (size_t)blockIdx.x * 128;

    // LN2 -> bf16
    #pragma unroll
    for (int ni = 0; ni < 8; ni++) {
        const int n = wp * 8 + ni;
        const float* yp = g_y + (p0 + n) * C_;
        float v[6]; float s = 0.f, s2 = 0.f;
        #pragma unroll
        for (int j = 0; j < 6; j++) { v[j] = yp[lane + 32 * j]; s += v[j]; s2 += v[j] * v[j]; }
        #pragma unroll
        for (int o = 16; o > 0; o >>= 1) {
            s  += __shfl_xor_sync(0xffffffffu, s,  o);
            s2 += __shfl_xor_sync(0xffffffffu, s2, o);
        }
        const float mean = s * (1.f / 192.f);
        const float rstd = rsqrtf(fmaxf(s2 * (1.f / 192.f) - mean * mean, 0.f) + 1e-5f);
        #pragma unroll
        for (int j = 0; j < 6; j++) {
            const int c = lane + 32 * j;
            a_s[n * LDH + c] = __float2bfloat16((v[j] - mean) * rstd * n2g[c] + n2b[c]);
        }
    }
    __syncthreads();

    // 2x3 warp tiling: rows {2mtp,2mtp+1} of 8, cols {3ctg..} of 12
    const int mtp = wp >> 2;
    const int ctB = (wp & 3) * 3;
    FragC acc2[6];
    #pragma unroll
    for (int j = 0; j < 6; j++) wmma::fill_fragment(acc2[j], 0.f);

    for (int hc = 0; hc < 4; hc++) {
        // ---- fc1 chunk ----
        FragC acc1[6];
        #pragma unroll
        for (int j = 0; j < 6; j++) wmma::fill_fragment(acc1[j], 0.f);

        float4 pre[3];
        #pragma unroll
        for (int i = 0; i < 3; i++) {
            const int idx = tid + 512 * i;
            const int r = idx / 48, c4 = (idx - r * 48) * 4;
            pre[i] = *(const float4*)(fc1w + (size_t)r * HIDDEN + hc * 192 + c4);
        }
        for (int kc = 0; kc < 6; kc++) {
            const int k0 = kc * 32;
            __nv_bfloat16* wbuf = w_s + (kc & 1) * 6400;
            #pragma unroll
            for (int i = 0; i < 3; i++) {
                const int idx = tid + 512 * i;
                const int r = idx / 48, c4 = (idx - r * 48) * 4;
                st_bf16x4(wbuf + r * LDH + c4, pre[i]);
            }
            if (kc < 5) {
                #pragma unroll
                for (int i = 0; i < 3; i++) {
                    const int idx = tid + 512 * i;
                    const int r = idx / 48, c4 = (idx - r * 48) * 4;
                    pre[i] = *(const float4*)(fc1w + (size_t)(k0 + 32 + r) * HIDDEN + hc * 192 + c4);
                }
            }
            __syncthreads();
            #pragma unroll
            for (int kk = 0; kk < 2; kk++) {
                FragA af[2];
                #pragma unroll
                for (int i = 0; i < 2; i++)
                    wmma::load_matrix_sync(af[i], a_s + (2 * mtp + i) * 16 * LDH + k0 + kk * 16, LDH);
                #pragma unroll
                for (int j = 0; j < 3; j++) {
                    FragB bf;
                    wmma::load_matrix_sync(bf, wbuf + kk * 16 * LDH + (ctB + j) * 16, LDH);
                    #pragma unroll
                    for (int i = 0; i < 2; i++) wmma::mma_sync(acc1[i * 3 + j], af[i], bf, acc1[i * 3 + j]);
                }
            }
        }
        __syncthreads();
        #pragma unroll
        for (int i = 0; i < 2; i++)
            #pragma unroll
            for (int j = 0; j < 3; j++)
                wmma::store_matrix_sync(t_f + (2 * mtp + i) * 16 * LDK + (ctB + j) * 16,
                                        acc1[i * 3 + j], LDK, wmma::mem_row_major);
        __syncthreads();
        // GELU + bias -> bf16
        for (int idx = tid; idx < 128 * 96; idx += 512) {
            const int n = idx / 96, c2 = (idx - n * 96) * 2;
            float v0 = t_f[n * LDK + c2]     + fc1b[hc * 192 + c2];
            float v1 = t_f[n * LDK + c2 + 1] + fc1b[hc * 192 + c2 + 1];
            v0 = 0.5f * v0 * (1.f + erff(v0 * 0.7071067811865476f));
            v1 = 0.5f * v1 * (1.f + erff(v1 * 0.7071067811865476f));
            *(__nv_bfloat162*)(t_s + n * LDH + c2) = __floats2bfloat162_rn(v0, v1);
        }
        __syncthreads();
        // ---- fc2 partial ----
        #pragma unroll
        for (int i = 0; i < 3; i++) {
            const int idx = tid + 512 * i;
            const int r = idx / 48, c4 = (idx - r * 48) * 4;
            pre[i] = *(const float4*)(fc2w + (size_t)(hc * 192 + r) * 192 + c4);
        }
        for (int kc = 0; kc < 6; kc++) {
            const int k0 = kc * 32;
            __nv_bfloat16* wbuf = w_s + (kc & 1) * 6400;
            #pragma unroll
            for (int i = 0; i < 3; i++) {
                const int idx = tid + 512 * i;
                const int r = idx / 48, c4 = (idx - r * 48) * 4;
                st_bf16x4(wbuf + r * LDH + c4, pre[i]);
            }
            if (kc < 5) {
                #pragma unroll
                for (int i = 0; i < 3; i++) {
                    const int idx = tid + 512 * i;
                    const int r = idx / 48, c4 = (idx - r * 48) * 4;
                    pre[i] = *(const float4*)(fc2w + (size_t)(hc * 192 + k0 + 32 + r) * 192 + c4);
                }
            }
            __syncthreads();
            #pragma unroll
            for (int kk = 0; kk < 2; kk++) {
                FragA af[2];
                #pragma unroll
                for (int i = 0; i < 2; i++)
                    wmma::load_matrix_sync(af[i], t_s + (2 * mtp + i) * 16 * LDH + k0 + kk * 16, LDH);
                #pragma unroll
                for (int j = 0; j < 3; j++) {
                    FragB bf;
                    wmma::load_matrix_sync(bf, wbuf + kk * 16 * LDH + (ctB + j) * 16, LDH);
                    #pragma unroll
                    for (int i = 0; i < 2; i++) wmma::mma_sync(acc2[i * 3 + j], af[i], bf, acc2[i * 3 + j]);
                }
            }
        }
        __syncthreads();
    }
    #pragma unroll
    for (int i = 0; i < 2; i++)
        #pragma unroll
        for (int j = 0; j < 3; j++)
            wmma::store_matrix_sync(t_f + (2 * mtp + i) * 16 * LDK + (ctB + j) * 16,
                                    acc2[i * 3 + j], LDK, wmma::mem_row_major);
    __syncthreads();

    // out = y + h2 + fc2_b
    for (int idx = tid; idx < 128 * 48; idx += 512) {
        const int n = idx / 48, c4 = (idx - n * 48) * 4;
        const size_t gp = (p0 + n) * C_ + c4;
        const float4 yv = *(const float4*)(g_y + gp);
        const float4 bb = *(const float4*)(fc2b + c4);
        const float* tt = t_f + n * LDK + c4;
        float4 o4;
        o4.x = yv.x + tt[0] + bb.x;
        o4.y = yv.y + tt[1] + bb.y;
        o4.z = yv.z + tt[2] + bb.z;
        o4.w = yv.w + tt[3] + bb.w;
        *(float4*)(out + gp) = o4;
    }
}

// ---------------------------------------------------------------------------
extern "C" void kernel_launch(void* const* d_in, const int* in_sizes, int n_in,
                              void* d_out, int out_size)
{
    const float* x     = (const float*)d_in[0];
    const float* qg    = (const float*)d_in[1];
    const float* n1g   = (const float*)d_in[2];
    const float* n1b   = (const float*)d_in[3];
    const float* qkvw  = (const float*)d_in[4];
    const float* qkvb  = (const float*)d_in[5];
    const float* rpb   = (const float*)d_in[6];
    const float* projw = (const float*)d_in[7];
    const float* projb = (const float*)d_in[8];
    const float* n2g   = (const float*)d_in[9];
    const float* n2b   = (const float*)d_in[10];
    const float* fc1w  = (const float*)d_in[11];
    const float* fc1b  = (const float*)d_in[12];
    const float* fc2w  = (const float*)d_in[13];
    const float* fc2b  = (const float*)d_in[14];
    float* out = (float*)d_out;

    cudaFuncSetAttribute(k_attn, cudaFuncAttributeMaxDynamicSharedMemorySize, 199680);
    cudaFuncSetAttribute(k_mlp,  cudaFuncAttributeMaxDynamicSharedMemorySize, 228352);

    k_attn<<<2048, 512, 199680>>>(x, qg, n1g, n1b, qkvw, qkvb, rpb, projw, projb);
    k_mlp <<<1024, 512, 228352>>>(n2g, n2b, fc1w, fc1b, fc2w, fc2b, out);
}

// round 17
// speedup vs baseline: 2.3870x; 1.0491x over previous
#include <cuda_runtime.h>
#include <cuda_bf16.h>
#include <mma.h>
#include <math.h>
#include <stdint.h>

using namespace nvcuda;

#define C_     192
#define LDH    200          // bf16 tile row stride (elements)
#define LDK    196          // fp32 scratch row stride (k_attn)
#define HIDDEN 768
#define NPIX   (32*64*64)

__device__ float g_y[(size_t)NPIX * C_];

__device__ __forceinline__ void st_bf16x4(__nv_bfloat16* dst, float4 v) {
    __nv_bfloat162 lo = __floats2bfloat162_rn(v.x, v.y);
    __nv_bfloat162 hi = __floats2bfloat162_rn(v.z, v.w);
    uint2 u; u.x = *(uint32_t*)&lo; u.y = *(uint32_t*)&hi;
    *(uint2*)dst = u;
}

typedef wmma::fragment<wmma::matrix_a, 16, 16, 16, __nv_bfloat16, wmma::row_major> FragA;
typedef wmma::fragment<wmma::matrix_b, 16, 16, 16, __nv_bfloat16, wmma::row_major> FragB;
typedef wmma::fragment<wmma::matrix_b, 16, 16, 16, __nv_bfloat16, wmma::col_major> FragBT;
typedef wmma::fragment<wmma::accumulator, 16, 16, 16, float> FragC;

// ---------------------------------------------------------------------------
// Kernel A (byte-identical to R8): per-window attention block
// grid = 2048, 512 threads, dynamic smem = 199680 B
// ---------------------------------------------------------------------------
__global__ __launch_bounds__(512) void k_attn(
    const float* __restrict__ x,     const float* __restrict__ qg,
    const float* __restrict__ n1g,   const float* __restrict__ n1b,
    const float* __restrict__ qkvw,  const float* __restrict__ qkvb,
    const float* __restrict__ rpb,
    const float* __restrict__ projw, const float* __restrict__ projb)
{
    extern __shared__ __align__(128) char sm[];
    __nv_bfloat16* sh_h = (__nv_bfloat16*)sm;
    __nv_bfloat16* kb   = (__nv_bfloat16*)(sm + 25600);
    __nv_bfloat16* vb   = (__nv_bfloat16*)(sm + 51200);
    __nv_bfloat16* qb   = (__nv_bfloat16*)(sm + 76800);
    char* big = sm + 101376;

    const int w  = blockIdx.x;
    const int b  = w >> 6, wy = (w >> 3) & 7, wx = w & 7;
    const int tid = threadIdx.x, lane = tid & 31, wp = tid >> 5;
    const int row0 = wy * 8, col0 = wx * 8;

    // ---------------- LN1 -> bf16 ----------------
    #pragma unroll
    for (int ni = 0; ni < 4; ni++) {
        const int n = wp * 4 + ni;
        const float* xp = x + ((size_t)((b * 64 + row0 + (n >> 3)) * 64 + col0 + (n & 7))) * C_;
        float v[6]; float s = 0.f, s2 = 0.f;
        #pragma unroll
        for (int j = 0; j < 6; j++) { v[j] = xp[lane + 32 * j]; s += v[j]; s2 += v[j] * v[j]; }
        #pragma unroll
        for (int o = 16; o > 0; o >>= 1) {
            s  += __shfl_xor_sync(0xffffffffu, s,  o);
            s2 += __shfl_xor_sync(0xffffffffu, s2, o);
        }
        const float mean = s * (1.f / 192.f);
        const float rstd = rsqrtf(fmaxf(s2 * (1.f / 192.f) - mean * mean, 0.f) + 1e-5f);
        #pragma unroll
        for (int j = 0; j < 6; j++) {
            const int c = lane + 32 * j;
            sh_h[n * LDH + c] = __float2bfloat16((v[j] - mean) * rstd * n1g[c] + n1b[c]);
        }
    }
    __syncthreads();

    // ---------------- QKV GEMM [64x192]@[192x384], double-buffered staging ----------------
    {
        const int ctBase = (wp >> 1) * 3;
        const int mt0    = (wp & 1) * 2;
        FragC acc[6];
        #pragma unroll
        for (int i = 0; i < 6; i++) wmma::fill_fragment(acc[i], 0.f);

        float4 pre[6];
        #pragma unroll
        for (int i = 0; i < 6; i++) {
            const int idx = tid + 512 * i;
            const int r = idx / 96, c4 = (idx - r * 96) * 4;
            pre[i] = *(const float4*)(qkvw + r * 384 + c4);
        }
        for (int kc = 0; kc < 6; kc++) {
            const int k0 = kc * 32;
            __nv_bfloat16* wbuf = (__nv_bfloat16*)(big + (kc & 1) * 25088);
            #pragma unroll
            for (int i = 0; i < 6; i++) {
                const int idx = tid + 512 * i;
                const int r = idx / 96, c4 = (idx - r * 96) * 4;
                st_bf16x4(wbuf + r * 392 + c4, pre[i]);
            }
            if (kc < 5) {
                #pragma unroll
                for (int i = 0; i < 6; i++) {
                    const int idx = tid + 512 * i;
                    const int r = idx / 96, c4 = (idx - r * 96) * 4;
                    pre[i] = *(const float4*)(qkvw + (k0 + 32 + r) * 384 + c4);
                }
            }
            __syncthreads();
            #pragma unroll
            for (int kk = 0; kk < 2; kk++) {
                FragA af[2];
                #pragma unroll
                for (int i = 0; i < 2; i++)
                    wmma::load_matrix_sync(af[i], sh_h + (mt0 + i) * 16 * LDH + k0 + kk * 16, LDH);
                #pragma unroll
                for (int j = 0; j < 3; j++) {
                    FragB bf;
                    wmma::load_matrix_sync(bf, wbuf + kk * 16 * 392 + (ctBase + j) * 16, 392);
                    #pragma unroll
                    for (int i = 0; i < 2; i++) wmma::mma_sync(acc[i * 3 + j], af[i], bf, acc[i * 3 + j]);
                }
            }
        }
        __syncthreads();
        float* qkv_f = (float*)big;
        #pragma unroll
        for (int i = 0; i < 2; i++)
            #pragma unroll
            for (int j = 0; j < 3; j++)
                wmma::store_matrix_sync(qkv_f + (mt0 + i) * 16 * 384 + (ctBase + j) * 16,
                                        acc[i * 3 + j], 384, wmma::mem_row_major);
    }
    __syncthreads();

    // ---------------- convert K,V (+bias) -> bf16; q*scale -> bf16 ----------------
    {
        float* qkv_f = (float*)big;
        for (int idx = tid; idx < 64 * 96; idx += 512) {
            const int n = idx / 96, c2 = (idx - n * 96) * 2;
            float k0v = qkv_f[n * 384 + c2]       + qkvb[c2];
            float k1v = qkv_f[n * 384 + c2 + 1]   + qkvb[c2 + 1];
            *(__nv_bfloat162*)(kb + n * LDH + c2) = __floats2bfloat162_rn(k0v, k1v);
            float v0v = qkv_f[n * 384 + 192 + c2]     + qkvb[192 + c2];
            float v1v = qkv_f[n * 384 + 192 + c2 + 1] + qkvb[192 + c2 + 1];
            *(__nv_bfloat162*)(vb + n * LDH + c2) = __floats2bfloat162_rn(v0v, v1v);
        }
        for (int idx = tid; idx < 12288; idx += 512) {
            const int d = idx & 31, n = (idx >> 5) & 63, h = idx >> 11;
            qb[h * 2048 + n * 32 + d] =
                __float2bfloat16(qg[(((size_t)b * 64 + n) * 6 + h) * 32 + d] * 0.17677669529663688f);
        }
    }
    __syncthreads();

    // ---------------- S = Q K^T (96 tiles, 6 per warp) ----------------
    {
        float* s_f = (float*)big;
        #pragma unroll
        for (int j = 0; j < 6; j++) {
            const int t = wp + (j << 4);
            const int head = t >> 4, sub = t & 15, mi = sub >> 2, ni = sub & 3;
            FragC acc;
            wmma::fill_fragment(acc, 0.f);
            #pragma unroll
            for (int kk = 0; kk < 2; kk++) {
                FragA af;
                wmma::load_matrix_sync(af, qb + head * 2048 + mi * 16 * 32 + kk * 16, 32);
                FragBT bf;
                wmma::load_matrix_sync(bf, kb + ni * 16 * LDH + head * 32 + kk * 16, LDH);
                wmma::mma_sync(acc, af, bf, acc);
            }
            wmma::store_matrix_sync(s_f + head * 4096 + mi * 16 * 64 + ni * 16, acc, 64,
                                    wmma::mem_row_major);
        }
    }
    __syncthreads();

    // ---------------- softmax rows (fp32), write P bf16 in place ----------------
    {
        float* s_f = (float*)big;
        #pragma unroll 4
        for (int it = 0; it < 24; it++) {
            const int t = wp + (it << 4);
            const int head = t >> 6, i = t & 63;
            const int iy = i >> 3, ix = i & 7;
            const int j0 = lane * 2;
            float s0 = s_f[head * 4096 + i * 64 + j0];
            float s1 = s_f[head * 4096 + i * 64 + j0 + 1];
            const int jy0 = j0 >> 3,       jx0 = j0 & 7;
            const int jy1 = (j0 + 1) >> 3, jx1 = (j0 + 1) & 7;
            s0 += rpb[((iy - jy0 + 7) * 15 + (ix - jx0 + 7)) * 6 + head];
            s1 += rpb[((iy - jy1 + 7) * 15 + (ix - jx1 + 7)) * 6 + head];
            float mx = fmaxf(s0, s1);
            #pragma unroll
            for (int o = 16; o > 0; o >>= 1) mx = fmaxf(mx, __shfl_xor_sync(0xffffffffu, mx, o));
            const float e0 = __expf(s0 - mx), e1 = __expf(s1 - mx);
            float sum = e0 + e1;
            #pragma unroll
            for (int o = 16; o > 0; o >>= 1) sum += __shfl_xor_sync(0xffffffffu, sum, o);
            const float inv = 1.f / sum;
            __nv_bfloat16* pr = (__nv_bfloat16*)(s_f + head * 4096 + i * 64);
            *(__nv_bfloat162*)(pr + j0) = __floats2bfloat162_rn(e0 * inv, e1 * inv);
        }
    }
    __syncthreads();

    // ---------------- O = P V (48 tiles, 3 per warp) ----------------
    {
        __nv_bfloat16* pb = (__nv_bfloat16*)big;
        FragC acc[3];
        int hh[3], mm[3], nn[3];
        #pragma unroll
        for (int j = 0; j < 3; j++) {
            const int t = wp + (j << 4);
            hh[j] = t >> 3; mm[j] = (t & 7) >> 1; nn[j] = t & 1;
            wmma::fill_fragment(acc[j], 0.f);
            #pragma unroll
            for (int kk = 0; kk < 4; kk++) {
                FragA af;
                wmma::load_matrix_sync(af, pb + hh[j] * 8192 + mm[j] * 16 * 128 + kk * 16, 128);
                FragB bf;
                wmma::load_matrix_sync(bf, vb + kk * 16 * LDH + hh[j] * 32 + nn[j] * 16, LDH);
                wmma::mma_sync(acc[j], af, bf, acc[j]);
            }
        }
        __syncthreads();
        float* o_f = (float*)big;
        #pragma unroll
        for (int j = 0; j < 3; j++)
            wmma::store_matrix_sync(o_f + mm[j] * 16 * LDK + hh[j] * 32 + nn[j] * 16, acc[j], LDK,
                                    wmma::mem_row_major);
    }
    __syncthreads();

    // ---------------- convert o -> sh_h bf16 ----------------
    {
        float* o_f = (float*)big;
        for (int idx = tid; idx < 64 * 96; idx += 512) {
            const int n = idx / 96, c2 = (idx - n * 96) * 2;
            *(__nv_bfloat162*)(sh_h + n * LDH + c2) =
                __floats2bfloat162_rn(o_f[n * LDK + c2], o_f[n * LDK + c2 + 1]);
        }
    }
    __syncthreads();

    // ---------------- proj [64x192]@[192x192], double-buffered ----------------
    {
        const int mt  = wp >> 2;
        const int ctB = (wp & 3) * 3;
        FragC acc[3];
        #pragma unroll
        for (int j = 0; j < 3; j++) wmma::fill_fragment(acc[j], 0.f);

        float4 pre[6];
        #pragma unroll
        for (int i = 0; i < 6; i++) {
            const int idx = tid + 512 * i;
            const int r = idx / 48, c4 = (idx - r * 48) * 4;
            pre[i] = *(const float4*)(projw + r * 192 + c4);
        }
        for (int kc = 0; kc < 3; kc++) {
            const int k0 = kc * 64;
            __nv_bfloat16* wbuf = (__nv_bfloat16*)(big + (kc & 1) * 25600);
            #pragma unroll
            for (int i = 0; i < 6; i++) {
                const int idx = tid + 512 * i;
                const int r = idx / 48, c4 = (idx - r * 48) * 4;
                st_bf16x4(wbuf + r * LDH + c4, pre[i]);
            }
            if (kc < 2) {
                #pragma unroll
                for (int i = 0; i < 6; i++) {
                    const int idx = tid + 512 * i;
                    const int r = idx / 48, c4 = (idx - r * 48) * 4;
                    pre[i] = *(const float4*)(projw + (k0 + 64 + r) * 192 + c4);
                }
            }
            __syncthreads();
            #pragma unroll
            for (int kk = 0; kk < 4; kk++) {
                FragA af;
                wmma::load_matrix_sync(af, sh_h + mt * 16 * LDH + k0 + kk * 16, LDH);
                #pragma unroll
                for (int j = 0; j < 3; j++) {
                    FragB bf;
                    wmma::load_matrix_sync(bf, wbuf + kk * 16 * LDH + (ctB + j) * 16, LDH);
                    wmma::mma_sync(acc[j], af, bf, acc[j]);
                }
            }
        }
        __syncthreads();
        float* proj_f = (float*)big;
        #pragma unroll
        for (int j = 0; j < 3; j++)
            wmma::store_matrix_sync(proj_f + mt * 16 * LDK + (ctB + j) * 16, acc[j], LDK,
                                    wmma::mem_row_major);
    }
    __syncthreads();

    // ---------------- y = x + proj + proj_b -> g_y ----------------
    {
        float* proj_f = (float*)big;
        for (int idx = tid; idx < 3072; idx += 512) {
            const int n = idx / 48, c4 = (idx - n * 48) * 4;
            const int iy = n >> 3, ix = n & 7;
            const size_t gp = ((size_t)((b * 64 + row0 + iy) * 64 + col0 + ix)) * C_ + c4;
            const float4 xv = *(const float4*)(x + gp);
            const float4 pb4 = *(const float4*)(projb + c4);
            const float* yt = proj_f + n * LDK + c4;
            float4 o4;
            o4.x = xv.x + yt[0] + pb4.x;
            o4.y = xv.y + yt[1] + pb4.y;
            o4.z = xv.z + yt[2] + pb4.z;
            o4.w = xv.w + yt[3] + pb4.w;
            *(float4*)(g_y + gp) = o4;
        }
    }
}

// ---------------------------------------------------------------------------
// Kernel B v2: 64-token CTAs, 256 threads, 2 CTAs/SM for cross-CTA overlap.
// grid = 2048, dynamic smem = 87040 B
//   a_s bf16 [64][200]  @0       25600
//   t_s bf16 [64][200]  @25600   25600
//   w_s bf16 2x[32][200]@51200   25600
//   ws  f32  per-warp [16][20] x8 @76800  10240
// ---------------------------------------------------------------------------
__global__ __launch_bounds__(256, 2) void k_mlp(
    const float* __restrict__ n2g,  const float* __restrict__ n2b,
    const float* __restrict__ fc1w, const float* __restrict__ fc1b,
    const float* __restrict__ fc2w, const float* __restrict__ fc2b,
    float* __restrict__ out)
{
    extern __shared__ __align__(128) char sm[];
    __nv_bfloat16* a_s = (__nv_bfloat16*)sm;
    __nv_bfloat16* t_s = (__nv_bfloat16*)(sm + 25600);
    __nv_bfloat16* w_s = (__nv_bfloat16*)(sm + 51200);
    const int tid = threadIdx.x, lane = tid & 31, wp = tid >> 5;
    float* wsw = (float*)(sm + 76800 + wp * 1280);     // [16][20] per warp
    const size_t p0 = (size_t)blockIdx.x * 64;

    // LN2 -> a_s bf16 (8 tokens per warp)
    #pragma unroll
    for (int ni = 0; ni < 8; ni++) {
        const int n = wp * 8 + ni;
        const float* yp = g_y + (p0 + n) * C_;
        float v[6]; float s = 0.f, s2 = 0.f;
        #pragma unroll
        for (int j = 0; j < 6; j++) { v[j] = yp[lane + 32 * j]; s += v[j]; s2 += v[j] * v[j]; }
        #pragma unroll
        for (int o = 16; o > 0; o >>= 1) {
            s  += __shfl_xor_sync(0xffffffffu, s,  o);
            s2 += __shfl_xor_sync(0xffffffffu, s2, o);
        }
        const float mean = s * (1.f / 192.f);
        const float rstd = rsqrtf(fmaxf(s2 * (1.f / 192.f) - mean * mean, 0.f) + 1e-5f);
        #pragma unroll
        for (int j = 0; j < 6; j++) {
            const int c = lane + 32 * j;
            a_s[n * LDH + c] = __float2bfloat16((v[j] - mean) * rstd * n2g[c] + n2b[c]);
        }
    }
    __syncthreads();

    // warp tiling: row tiles {2mtp, 2mtp+1} of 4, col tiles ctB..ctB+2 of 12
    const int mtp = wp >> 2;
    const int ctB = (wp & 3) * 3;
    FragC acc2[6];
    #pragma unroll
    for (int j = 0; j < 6; j++) wmma::fill_fragment(acc2[j], 0.f);

    for (int hc = 0; hc < 4; hc++) {
        // ---- fc1 chunk: acc1 = a_s @ W1[:, hc*192:+192] ----
        FragC acc1[6];
        #pragma unroll
        for (int j = 0; j < 6; j++) wmma::fill_fragment(acc1[j], 0.f);
        for (int kc = 0; kc < 6; kc++) {
            const int k0 = kc * 32;
            __nv_bfloat16* wbuf = w_s + (kc & 1) * 6400;
            #pragma unroll
            for (int i = 0; i < 6; i++) {
                const int idx = tid + 256 * i;
                const int r = idx / 48, c4 = (idx - r * 48) * 4;
                st_bf16x4(wbuf + r * LDH + c4,
                          *(const float4*)(fc1w + (size_t)(k0 + r) * HIDDEN + hc * 192 + c4));
            }
            __syncthreads();
            #pragma unroll
            for (int kk = 0; kk < 2; kk++) {
                FragA af[2];
                #pragma unroll
                for (int i = 0; i < 2; i++)
                    wmma::load_matrix_sync(af[i], a_s + (2 * mtp + i) * 16 * LDH + k0 + kk * 16, LDH);
                #pragma unroll
                for (int j = 0; j < 3; j++) {
                    FragB bf;
                    wmma::load_matrix_sync(bf, wbuf + kk * 16 * LDH + (ctB + j) * 16, LDH);
                    #pragma unroll
                    for (int i = 0; i < 2; i++) wmma::mma_sync(acc1[i * 3 + j], af[i], bf, acc1[i * 3 + j]);
                }
            }
        }
        // ---- GELU + bias via warp-private scratch -> t_s bf16 ----
        #pragma unroll
        for (int i = 0; i < 2; i++) {
            #pragma unroll
            for (int j = 0; j < 3; j++) {
                wmma::store_matrix_sync(wsw, acc1[i * 3 + j], 20, wmma::mem_row_major);
                __syncwarp();
                const int rowB = (2 * mtp + i) * 16;
                const int colB = (ctB + j) * 16;
                #pragma unroll
                for (int e = 0; e < 4; e++) {
                    const int idx = lane * 4 + e;       // 128 bf16x2 pairs
                    const int r = idx >> 3, c2 = (idx & 7) * 2;
                    float v0 = wsw[r * 20 + c2]     + fc1b[hc * 192 + colB + c2];
                    float v1 = wsw[r * 20 + c2 + 1] + fc1b[hc * 192 + colB + c2 + 1];
                    v0 = 0.5f * v0 * (1.f + erff(v0 * 0.7071067811865476f));
                    v1 = 0.5f * v1 * (1.f + erff(v1 * 0.7071067811865476f));
                    *(__nv_bfloat162*)(t_s + (rowB + r) * LDH + colB + c2) =
                        __floats2bfloat162_rn(v0, v1);
                }
                __syncwarp();
            }
        }
        // ---- fc2 partial: acc2 += t_s @ W2[hc*192:+192, :] ----
        for (int kc = 0; kc < 6; kc++) {
            const int k0 = kc * 32;
            __nv_bfloat16* wbuf = w_s + (kc & 1) * 6400;
            #pragma unroll
            for (int i = 0; i < 6; i++) {
                const int idx = tid + 256 * i;
                const int r = idx / 48, c4 = (idx - r * 48) * 4;
                st_bf16x4(wbuf + r * LDH + c4,
                          *(const float4*)(fc2w + (size_t)(hc * 192 + k0 + r) * 192 + c4));
            }
            __syncthreads();                             // also orders t_s writes before reads (kc=0)
            #pragma unroll
            for (int kk = 0; kk < 2; kk++) {
                FragA af[2];
                #pragma unroll
                for (int i = 0; i < 2; i++)
                    wmma::load_matrix_sync(af[i], t_s + (2 * mtp + i) * 16 * LDH + k0 + kk * 16, LDH);
                #pragma unroll
                for (int j = 0; j < 3; j++) {
                    FragB bf;
                    wmma::load_matrix_sync(bf, wbuf + kk * 16 * LDH + (ctB + j) * 16, LDH);
                    #pragma unroll
                    for (int i = 0; i < 2; i++) wmma::mma_sync(acc2[i * 3 + j], af[i], bf, acc2[i * 3 + j]);
                }
            }
        }
        __syncthreads();                                 // wbuf/t_s reads done before next hc rewrites
    }

    // ---- epilogue: out = y + acc2 + fc2_b (warp-private scratch) ----
    #pragma unroll
    for (int i = 0; i < 2; i++) {
        #pragma unroll
        for (int j = 0; j < 3; j++) {
            wmma::store_matrix_sync(wsw, acc2[i * 3 + j], 20, wmma::mem_row_major);
            __syncwarp();
            const int rowB = (2 * mtp + i) * 16;
            const int colB = (ctB + j) * 16;
            #pragma unroll
            for (int e = 0; e < 2; e++) {
                const int idx = lane * 2 + e;            // 64 float4 groups
                const int r = idx >> 2, c0 = (idx & 3) * 4;
                const size_t gp = (p0 + rowB + r) * C_ + colB + c0;
                const float4 yv = *(const float4*)(g_y + gp);
                float4 o4;
                o4.x = yv.x + wsw[r * 20 + c0]     + fc2b[colB + c0];
                o4.y = yv.y + wsw[r * 20 + c0 + 1] + fc2b[colB + c0 + 1];
                o4.z = yv.z + wsw[r * 20 + c0 + 2] + fc2b[colB + c0 + 2];
                o4.w = yv.w + wsw[r * 20 + c0 + 3] + fc2b[colB + c0 + 3];
                *(float4*)(out + gp) = o4;
            }
            __syncwarp();
        }
    }
}

// ---------------------------------------------------------------------------
extern "C" void kernel_launch(void* const* d_in, const int* in_sizes, int n_in,
                              void* d_out, int out_size)
{
    const float* x     = (const float*)d_in[0];
    const float* qg    = (const float*)d_in[1];
    const float* n1g   = (const float*)d_in[2];
    const float* n1b   = (const float*)d_in[3];
    const float* qkvw  = (const float*)d_in[4];
    const float* qkvb  = (const float*)d_in[5];
    const float* rpb   = (const float*)d_in[6];
    const float* projw = (const float*)d_in[7];
    const float* projb = (const float*)d_in[8];
    const float* n2g   = (const float*)d_in[9];
    const float* n2b   = (const float*)d_in[10];
    const float* fc1w  = (const float*)d_in[11];
    const float* fc1b  = (const float*)d_in[12];
    const float* fc2w  = (const float*)d_in[13];
    const float* fc2b  = (const float*)d_in[14];
    float* out = (float*)d_out;

    cudaFuncSetAttribute(k_attn, cudaFuncAttributeMaxDynamicSharedMemorySize, 199680);
    cudaFuncSetAttribute(k_mlp,  cudaFuncAttributeMaxDynamicSharedMemorySize, 87040);

    k_attn<<<2048, 512, 199680>>>(x, qg, n1g, n1b, qkvw, qkvb, rpb, projw, projb);
    k_mlp <<<2048, 256, 87040>>>(n2g, n2b, fc1w, fc1b, fc2w, fc2b, out);
}